// round 8
// baseline (speedup 1.0000x reference)
#include <cuda_runtime.h>
#include <cstdint>

// Problem constants
#define BB   2
#define TT   2048
#define CCH  1024
#define HH   16
#define HDIM 64
#define NTOK (BB * TT)     // 4096
#define C3   (3 * CCH)     // 3072

// Scratch (allocation-free rule: __device__ globals)
__device__ float g_qkv[(size_t)NTOK * C3];    // [4096, 3072]
__device__ float g_att[(size_t)NTOK * CCH];   // [4096, 1024]
__device__ float g_wqkvT[(size_t)C3 * CCH];   // Wqkv^T [3072,1024]
__device__ float g_woT[(size_t)CCH * CCH];    // Wo^T   [1024,1024]

// ---------------------------------------------------------------------------
// helpers
// ---------------------------------------------------------------------------
__device__ __forceinline__ uint32_t smem_u32(const void* p) {
    uint32_t a;
    asm("{ .reg .u64 t; cvta.to.shared.u64 t, %1; cvt.u32.u64 %0, t; }" : "=r"(a) : "l"(p));
    return a;
}

__device__ __forceinline__ void cp_async16(uint32_t saddr, const void* gaddr) {
    asm volatile("cp.async.ca.shared.global [%0], [%1], 16;" :: "r"(saddr), "l"(gaddr) : "memory");
}
#define CP_COMMIT() asm volatile("cp.async.commit_group;" ::: "memory")
#define CP_WAIT(n)  asm volatile("cp.async.wait_group %0;" :: "n"(n) : "memory")

__device__ __forceinline__ void mma_tf32(float* c, const uint32_t* a, const uint32_t* b) {
    asm volatile(
        "mma.sync.aligned.m16n8k8.row.col.f32.tf32.tf32.f32 "
        "{%0,%1,%2,%3}, {%4,%5,%6,%7}, {%8,%9}, {%0,%1,%2,%3};"
        : "+f"(c[0]), "+f"(c[1]), "+f"(c[2]), "+f"(c[3])
        : "r"(a[0]), "r"(a[1]), "r"(a[2]), "r"(a[3]), "r"(b[0]), "r"(b[1]));
}

// round-to-nearest fp32 -> tf32
__device__ __forceinline__ uint32_t f2tf(float x) {
    uint32_t r;
    asm("cvt.rna.tf32.f32 %0, %1;" : "=r"(r) : "f"(x));
    return r;
}
__device__ __forceinline__ void tf32_split(float x, uint32_t& hi, uint32_t& lo) {
    hi = f2tf(x);
    lo = f2tf(x - __uint_as_float(hi));
}
// split to float-typed hi/lo (both tf32-valued)
__device__ __forceinline__ void tf32_split_f(float x, float& hi, float& lo) {
    uint32_t h = f2tf(x);
    hi = __uint_as_float(h);
    lo = __uint_as_float(f2tf(x - hi));
}

// MUFU-free 2^u for u <= 0 (softmax probabilities). ~2e-6 rel accuracy.
__device__ __forceinline__ float exp2p(float u) {
    u = fmaxf(u, -126.f);
    float z = u + 12582912.f;                       // round-to-int magic (1.5*2^23)
    int ki = __float_as_int(z) - 0x4B400000;        // = rint(u)
    float r = u - (z - 12582912.f);                 // r in [-0.5, 0.5]
    float p = 0.00133336f;
    p = fmaf(p, r, 0.00961813f);
    p = fmaf(p, r, 0.05550411f);
    p = fmaf(p, r, 0.24022651f);
    p = fmaf(p, r, 0.69314718f);
    p = fmaf(p, r, 1.0f);
    return __int_as_float(__float_as_int(p) + (ki << 23));
}

// ---------------------------------------------------------------------------
// 32x32 tiled transpose
// ---------------------------------------------------------------------------
__global__ void __launch_bounds__(256) transpose_k(
    const float* __restrict__ in, float* __restrict__ out, int R, int Cc)
{
    __shared__ float t[32][33];
    const int c0 = blockIdx.x * 32, r0 = blockIdx.y * 32;
    const int x = threadIdx.x, y = threadIdx.y;
#pragma unroll
    for (int i = 0; i < 32; i += 8)
        t[y + i][x] = in[(size_t)(r0 + y + i) * Cc + c0 + x];
    __syncthreads();
#pragma unroll
    for (int i = 0; i < 32; i += 8)
        out[(size_t)(c0 + y + i) * R + r0 + x] = t[x][y + i];
}

// ---------------------------------------------------------------------------
// 3xTF32 warp-MMA GEMM (unchanged from R6 — passed at ~170 TF/s issued)
// ---------------------------------------------------------------------------
#define PITCH 36
#define STG_BYTES (128 * PITCH * 4)
#define SMEM_GEMM (4 * STG_BYTES)

__global__ void __launch_bounds__(256) gemm_mma(
    const float* __restrict__ A, const float* __restrict__ BT,
    const float* __restrict__ bias, float* __restrict__ C,
    int N, int K)
{
    extern __shared__ char smem[];
    float* As[2] = { (float*)smem,                   (float*)(smem + 2 * STG_BYTES) };
    float* Bs[2] = { (float*)(smem + STG_BYTES),     (float*)(smem + 3 * STG_BYTES) };
    const uint32_t sAu[2] = { smem_u32(As[0]), smem_u32(As[1]) };
    const uint32_t sBu[2] = { smem_u32(Bs[0]), smem_u32(Bs[1]) };

    const int tid = threadIdx.x;
    const int lane = tid & 31;
    const int wid = tid >> 5;
    const int wm = (wid & 1) * 64;
    const int wn = (wid >> 1) * 32;
    const int g = lane >> 2;
    const int t = lane & 3;

    const int row0 = blockIdx.y * 128;
    const int col0 = blockIdx.x * 128;

    const int ldrow = tid >> 3;
    const int ldc4  = tid & 7;

    float c[4][4][4];
#pragma unroll
    for (int mf = 0; mf < 4; mf++)
#pragma unroll
        for (int nf = 0; nf < 4; nf++)
#pragma unroll
            for (int i = 0; i < 4; i++) c[mf][nf][i] = 0.f;

    const int niter = K / 32;

#define LOAD_STAGE(it, buf)                                                     \
    {                                                                           \
        const int k0_ = (it) * 32;                                              \
        _Pragma("unroll")                                                       \
        for (int i = 0; i < 4; i++) {                                           \
            const int r = ldrow + i * 32;                                       \
            const uint32_t so = (uint32_t)(r * PITCH + ldc4 * 4) * 4;           \
            cp_async16(sAu[buf] + so, A  + (size_t)(row0 + r) * K + k0_ + ldc4 * 4); \
            cp_async16(sBu[buf] + so, BT + (size_t)(col0 + r) * K + k0_ + ldc4 * 4); \
        }                                                                       \
        CP_COMMIT();                                                            \
    }

    LOAD_STAGE(0, 0);
    LOAD_STAGE(1, 1);
    CP_WAIT(1);
    __syncthreads();

    for (int it = 0; it < niter; it++) {
        const int buf = it & 1;
        const float* Ab = As[buf];
        const float* Bb = Bs[buf];

#pragma unroll
        for (int ks = 0; ks < 4; ks++) {
            const int k = ks * 8 + t;
            uint32_t ah[4][4], al[4][4], bh[4][2], bl[4][2];
#pragma unroll
            for (int mf = 0; mf < 4; mf++) {
                const int base = (wm + mf * 16 + g) * PITCH + k;
                tf32_split(Ab[base],                 ah[mf][0], al[mf][0]);
                tf32_split(Ab[base + 8 * PITCH],     ah[mf][1], al[mf][1]);
                tf32_split(Ab[base + 4],             ah[mf][2], al[mf][2]);
                tf32_split(Ab[base + 8 * PITCH + 4], ah[mf][3], al[mf][3]);
            }
#pragma unroll
            for (int nf = 0; nf < 4; nf++) {
                const int base = (wn + nf * 8 + g) * PITCH + k;
                tf32_split(Bb[base],     bh[nf][0], bl[nf][0]);
                tf32_split(Bb[base + 4], bh[nf][1], bl[nf][1]);
            }
#pragma unroll
            for (int mf = 0; mf < 4; mf++)
#pragma unroll
                for (int nf = 0; nf < 4; nf++) {
                    mma_tf32(c[mf][nf], al[mf], bh[nf]);
                    mma_tf32(c[mf][nf], ah[mf], bl[nf]);
                    mma_tf32(c[mf][nf], ah[mf], bh[nf]);
                }
        }

        __syncthreads();
        if (it + 2 < niter) {
            LOAD_STAGE(it + 2, buf);
            CP_WAIT(1);
        } else {
            CP_WAIT(0);
        }
        __syncthreads();
    }
#undef LOAD_STAGE

#pragma unroll
    for (int mf = 0; mf < 4; mf++) {
        const int r0_ = row0 + wm + mf * 16 + g;
#pragma unroll
        for (int nf = 0; nf < 4; nf++) {
            const int cc = col0 + wn + nf * 8 + t * 2;
            const float b0 = bias[cc], b1 = bias[cc + 1];
            float2 lo = make_float2(c[mf][nf][0] + b0, c[mf][nf][1] + b1);
            float2 hi = make_float2(c[mf][nf][2] + b0, c[mf][nf][3] + b1);
            *(float2*)&C[(size_t)r0_ * N + cc]       = lo;
            *(float2*)&C[(size_t)(r0_ + 8) * N + cc] = hi;
        }
    }
}

// ---------------------------------------------------------------------------
// 3xTF32 flash attention.
// 4 warps / CTA, 64 q-rows per CTA (16 per warp), kv tiles of 64.
// grid: x = 32 q-tiles (reversed for load balance), y = B*H.
// smem (floats): Khi/Klo [64][68], Vthi/Vtlo [64][68] (V transposed),
//                Phi/Plo per-warp [16][68].
// ---------------------------------------------------------------------------
#define APITCH 68
#define KHI_OFF  0
#define KLO_OFF  4352
#define VTHI_OFF 8704
#define VTLO_OFF 13056
#define P_OFF    17408                    // PHI then PLO (4352 floats each)
#define ATT_FLOATS 26112
#define ATT_SMEM (ATT_FLOATS * 4)         // 104448 bytes

__global__ void __launch_bounds__(128) attn_mma(
    const float* __restrict__ qkv, float* __restrict__ out)
{
    extern __shared__ float sm[];
    const int tid = threadIdx.x;
    const int lane = tid & 31;
    const int wid = tid >> 5;
    const int g = lane >> 2;       // 0..7
    const int t = lane & 3;        // 0..3

    const int bh = blockIdx.y;
    const int b = bh >> 4;
    const int h = bh & 15;
    const int qtile = (int)gridDim.x - 1 - (int)blockIdx.x;   // heavy blocks first
    const int q0 = qtile * 64;

    float* PHI = sm + P_OFF + wid * 1088;
    float* PLO = sm + P_OFF + 4352 + wid * 1088;

    // --- load Q fragments (persistent), scaled by 1/sqrt(64) * log2(e) ---
    const float QSCALE = 0.125f * 1.44269504f;
    const int grow0 = q0 + wid * 16 + g;
    const int grow1 = grow0 + 8;
    const float* q0p = qkv + (size_t)(b * TT + grow0) * C3 + h * HDIM;
    const float* q1p = q0p + (size_t)8 * C3;

    uint32_t qh[8][4], ql[8][4];
#pragma unroll
    for (int ks = 0; ks < 8; ks++) {
        tf32_split(q0p[ks * 8 + t]     * QSCALE, qh[ks][0], ql[ks][0]);
        tf32_split(q1p[ks * 8 + t]     * QSCALE, qh[ks][1], ql[ks][1]);
        tf32_split(q0p[ks * 8 + t + 4] * QSCALE, qh[ks][2], ql[ks][2]);
        tf32_split(q1p[ks * 8 + t + 4] * QSCALE, qh[ks][3], ql[ks][3]);
    }

    float o[8][4];
#pragma unroll
    for (int nf = 0; nf < 8; nf++)
#pragma unroll
        for (int i = 0; i < 4; i++) o[nf][i] = 0.f;
    float m0 = -1e30f, m1 = -1e30f, l0 = 0.f, l1 = 0.f;

    const int ntiles = qtile + 1;
    const float* kbase0 = qkv + (size_t)b * TT * C3 + CCH + h * HDIM;

    for (int tile = 0; tile < ntiles; tile++) {
        const int kv0 = tile * 64;
        const float* kb = kbase0 + (size_t)kv0 * C3;

        __syncthreads();   // previous tile fully consumed

        // --- stage K (split hi/lo, row-major [kv][d]) ---
#pragma unroll
        for (int i = 0; i < 8; i++) {
            const int idx = tid + i * 128;      // 0..1023 float4s
            const int r = idx >> 4, c4 = idx & 15;
            float4 kv4 = *(const float4*)(kb + (size_t)r * C3 + c4 * 4);
            float4 kh4, kl4;
            tf32_split_f(kv4.x, kh4.x, kl4.x);
            tf32_split_f(kv4.y, kh4.y, kl4.y);
            tf32_split_f(kv4.z, kh4.z, kl4.z);
            tf32_split_f(kv4.w, kh4.w, kl4.w);
            *(float4*)&sm[KHI_OFF + r * APITCH + c4 * 4] = kh4;
            *(float4*)&sm[KLO_OFF + r * APITCH + c4 * 4] = kl4;
        }
        // --- stage V transposed (4x4 register-block transpose, split hi/lo) ---
#pragma unroll
        for (int j = 0; j < 2; j++) {
            const int bb2 = tid + j * 128;       // 0..255 4x4 blocks
            const int br = (bb2 >> 4) * 4;       // kv base
            const int bc = (bb2 & 15) * 4;       // d base
            const float* vb = kb + CCH;
            float4 v0 = *(const float4*)(vb + (size_t)(br + 0) * C3 + bc);
            float4 v1 = *(const float4*)(vb + (size_t)(br + 1) * C3 + bc);
            float4 v2 = *(const float4*)(vb + (size_t)(br + 2) * C3 + bc);
            float4 v3 = *(const float4*)(vb + (size_t)(br + 3) * C3 + bc);
            float4 rowv[4] = {
                make_float4(v0.x, v1.x, v2.x, v3.x),
                make_float4(v0.y, v1.y, v2.y, v3.y),
                make_float4(v0.z, v1.z, v2.z, v3.z),
                make_float4(v0.w, v1.w, v2.w, v3.w)
            };
#pragma unroll
            for (int d = 0; d < 4; d++) {
                float4 hi4, lo4;
                tf32_split_f(rowv[d].x, hi4.x, lo4.x);
                tf32_split_f(rowv[d].y, hi4.y, lo4.y);
                tf32_split_f(rowv[d].z, hi4.z, lo4.z);
                tf32_split_f(rowv[d].w, hi4.w, lo4.w);
                *(float4*)&sm[VTHI_OFF + (bc + d) * APITCH + br] = hi4;
                *(float4*)&sm[VTLO_OFF + (bc + d) * APITCH + br] = lo4;
            }
        }
        __syncthreads();

        // --- S = Q K^T (3xTF32), log2-domain scores ---
        float s[8][4];
#pragma unroll
        for (int nf = 0; nf < 8; nf++) {
#pragma unroll
            for (int i = 0; i < 4; i++) s[nf][i] = 0.f;
            const int krow = (nf * 8 + g) * APITCH;
#pragma unroll
            for (int ks = 0; ks < 8; ks++) {
                uint32_t bh2[2], bl2[2];
                bh2[0] = __float_as_uint(sm[KHI_OFF + krow + ks * 8 + t]);
                bh2[1] = __float_as_uint(sm[KHI_OFF + krow + ks * 8 + t + 4]);
                bl2[0] = __float_as_uint(sm[KLO_OFF + krow + ks * 8 + t]);
                bl2[1] = __float_as_uint(sm[KLO_OFF + krow + ks * 8 + t + 4]);
                mma_tf32(s[nf], ql[ks], bh2);
                mma_tf32(s[nf], qh[ks], bl2);
                mma_tf32(s[nf], qh[ks], bh2);
            }
        }

        // --- causal mask (diagonal tile only) ---
        if (tile == qtile) {
#pragma unroll
            for (int nf = 0; nf < 8; nf++) {
                const int c0 = kv0 + nf * 8 + 2 * t;
                if (c0 > grow0)     s[nf][0] = -1e30f;
                if (c0 + 1 > grow0) s[nf][1] = -1e30f;
                if (c0 > grow1)     s[nf][2] = -1e30f;
                if (c0 + 1 > grow1) s[nf][3] = -1e30f;
            }
        }

        // --- online softmax (base 2) ---
        float tm0 = -1e30f, tm1 = -1e30f;
#pragma unroll
        for (int nf = 0; nf < 8; nf++) {
            tm0 = fmaxf(tm0, fmaxf(s[nf][0], s[nf][1]));
            tm1 = fmaxf(tm1, fmaxf(s[nf][2], s[nf][3]));
        }
        tm0 = fmaxf(tm0, __shfl_xor_sync(0xffffffffu, tm0, 1));
        tm0 = fmaxf(tm0, __shfl_xor_sync(0xffffffffu, tm0, 2));
        tm1 = fmaxf(tm1, __shfl_xor_sync(0xffffffffu, tm1, 1));
        tm1 = fmaxf(tm1, __shfl_xor_sync(0xffffffffu, tm1, 2));
        const float mn0 = fmaxf(m0, tm0);
        const float mn1 = fmaxf(m1, tm1);
        const float cr0 = exp2p(m0 - mn0);
        const float cr1 = exp2p(m1 - mn1);
        m0 = mn0; m1 = mn1;
        l0 *= cr0; l1 *= cr1;
#pragma unroll
        for (int nf = 0; nf < 8; nf++) {
            o[nf][0] *= cr0; o[nf][1] *= cr0;
            o[nf][2] *= cr1; o[nf][3] *= cr1;
        }

        // --- P = 2^(s-m), split hi/lo, store to per-warp smem ---
#pragma unroll
        for (int nf = 0; nf < 8; nf++) {
            const float p0 = exp2p(s[nf][0] - m0);
            const float p1 = exp2p(s[nf][1] - m0);
            const float p2 = exp2p(s[nf][2] - m1);
            const float p3 = exp2p(s[nf][3] - m1);
            l0 += p0 + p1;
            l1 += p2 + p3;
            float h0, lo0, h1, lo1, h2, lo2, h3, lo3;
            tf32_split_f(p0, h0, lo0);
            tf32_split_f(p1, h1, lo1);
            tf32_split_f(p2, h2, lo2);
            tf32_split_f(p3, h3, lo3);
            const int cidx = nf * 8 + 2 * t;
            *(float2*)&PHI[g * APITCH + cidx]       = make_float2(h0, h1);
            *(float2*)&PLO[g * APITCH + cidx]       = make_float2(lo0, lo1);
            *(float2*)&PHI[(g + 8) * APITCH + cidx] = make_float2(h2, h3);
            *(float2*)&PLO[(g + 8) * APITCH + cidx] = make_float2(lo2, lo3);
        }
        __syncwarp();

        // --- O += P V (3xTF32) ---
#pragma unroll
        for (int ks = 0; ks < 8; ks++) {
            uint32_t pah[4], pal[4];
            pah[0] = __float_as_uint(PHI[g * APITCH + ks * 8 + t]);
            pah[1] = __float_as_uint(PHI[(g + 8) * APITCH + ks * 8 + t]);
            pah[2] = __float_as_uint(PHI[g * APITCH + ks * 8 + t + 4]);
            pah[3] = __float_as_uint(PHI[(g + 8) * APITCH + ks * 8 + t + 4]);
            pal[0] = __float_as_uint(PLO[g * APITCH + ks * 8 + t]);
            pal[1] = __float_as_uint(PLO[(g + 8) * APITCH + ks * 8 + t]);
            pal[2] = __float_as_uint(PLO[g * APITCH + ks * 8 + t + 4]);
            pal[3] = __float_as_uint(PLO[(g + 8) * APITCH + ks * 8 + t + 4]);
#pragma unroll
            for (int nf = 0; nf < 8; nf++) {
                const int vrow = (nf * 8 + g) * APITCH;
                uint32_t vh[2], vl[2];
                vh[0] = __float_as_uint(sm[VTHI_OFF + vrow + ks * 8 + t]);
                vh[1] = __float_as_uint(sm[VTHI_OFF + vrow + ks * 8 + t + 4]);
                vl[0] = __float_as_uint(sm[VTLO_OFF + vrow + ks * 8 + t]);
                vl[1] = __float_as_uint(sm[VTLO_OFF + vrow + ks * 8 + t + 4]);
                mma_tf32(o[nf], pal, vh);
                mma_tf32(o[nf], pah, vl);
                mma_tf32(o[nf], pah, vh);
            }
        }
        __syncwarp();   // P consumed before next-tile overwrite
    }

    // --- finalize: reduce l across t-group, normalize, write out ---
    l0 += __shfl_xor_sync(0xffffffffu, l0, 1);
    l0 += __shfl_xor_sync(0xffffffffu, l0, 2);
    l1 += __shfl_xor_sync(0xffffffffu, l1, 1);
    l1 += __shfl_xor_sync(0xffffffffu, l1, 2);
    const float inv0 = 1.f / l0;
    const float inv1 = 1.f / l1;

    float* op0 = out + (size_t)(b * TT + grow0) * CCH + h * HDIM;
    float* op1 = out + (size_t)(b * TT + grow1) * CCH + h * HDIM;
#pragma unroll
    for (int nf = 0; nf < 8; nf++) {
        const int cidx = nf * 8 + 2 * t;
        *(float2*)&op0[cidx] = make_float2(o[nf][0] * inv0, o[nf][1] * inv0);
        *(float2*)&op1[cidx] = make_float2(o[nf][2] * inv1, o[nf][3] * inv1);
    }
}

// ---------------------------------------------------------------------------
extern "C" void kernel_launch(void* const* d_in, const int* in_sizes, int n_in,
                              void* d_out, int out_size)
{
    (void)in_sizes; (void)n_in; (void)out_size;
    const float* x    = (const float*)d_in[0];
    const float* Wqkv = (const float*)d_in[1];
    const float* bqkv = (const float*)d_in[2];
    const float* Wo   = (const float*)d_in[3];
    const float* bo   = (const float*)d_in[4];
    float* out = (float*)d_out;

    float *qkvbuf, *attbuf, *wqkvT, *woT;
    cudaGetSymbolAddress((void**)&qkvbuf, g_qkv);
    cudaGetSymbolAddress((void**)&attbuf, g_att);
    cudaGetSymbolAddress((void**)&wqkvT, g_wqkvT);
    cudaGetSymbolAddress((void**)&woT, g_woT);

    static int smem_set = 0;
    if (!smem_set) {
        cudaFuncSetAttribute(gemm_mma, cudaFuncAttributeMaxDynamicSharedMemorySize, SMEM_GEMM);
        cudaFuncSetAttribute(attn_mma, cudaFuncAttributeMaxDynamicSharedMemorySize, ATT_SMEM);
        smem_set = 1;
    }

    // 0) transpose weights -> col-major B operands
    transpose_k<<<dim3(C3 / 32, CCH / 32), dim3(32, 8)>>>(Wqkv, wqkvT, CCH, C3);
    transpose_k<<<dim3(CCH / 32, CCH / 32), dim3(32, 8)>>>(Wo, woT, CCH, CCH);

    // 1) QKV projection (3xTF32 warp MMA)
    gemm_mma<<<dim3(C3 / 128, NTOK / 128), 256, SMEM_GEMM>>>(x, wqkvT, bqkv, qkvbuf, C3, CCH);

    // 2) causal flash attention (3xTF32 warp MMA)
    attn_mma<<<dim3(TT / 64, BB * HH), 128, ATT_SMEM>>>(qkvbuf, attbuf);

    // 3) output projection (3xTF32 warp MMA)
    gemm_mma<<<dim3(CCH / 128, NTOK / 128), 256, SMEM_GEMM>>>(attbuf, woT, bo, out, CCH, CCH);
}

// round 9
// speedup vs baseline: 1.5057x; 1.5057x over previous
#include <cuda_runtime.h>
#include <cstdint>

// Problem constants
#define BB   2
#define TT   2048
#define CCH  1024
#define HH   16
#define HDIM 64
#define NTOK (BB * TT)     // 4096
#define C3   (3 * CCH)     // 3072

// Scratch (allocation-free rule: __device__ globals)
__device__ float  g_qkv[(size_t)NTOK * C3];     // [4096, 3072] fp32
__device__ float  g_att[(size_t)NTOK * CCH];    // [4096, 1024] fp32
__device__ float2 g_x2[(size_t)NTOK * CCH];     // x split hi/lo
__device__ float2 g_att2[(size_t)NTOK * CCH];   // att split hi/lo
__device__ float2 g_wqkvT2[(size_t)C3 * CCH];   // Wqkv^T split [3072][1024]
__device__ float2 g_woT2[(size_t)CCH * CCH];    // Wo^T split [1024][1024]

// ---------------------------------------------------------------------------
// helpers
// ---------------------------------------------------------------------------
__device__ __forceinline__ uint32_t smem_u32(const void* p) {
    uint32_t a;
    asm("{ .reg .u64 t; cvta.to.shared.u64 t, %1; cvt.u32.u64 %0, t; }" : "=r"(a) : "l"(p));
    return a;
}

__device__ __forceinline__ void cp_async16(uint32_t saddr, const void* gaddr) {
    asm volatile("cp.async.ca.shared.global [%0], [%1], 16;" :: "r"(saddr), "l"(gaddr) : "memory");
}
#define CP_COMMIT() asm volatile("cp.async.commit_group;" ::: "memory")
#define CP_WAIT(n)  asm volatile("cp.async.wait_group %0;" :: "n"(n) : "memory")

__device__ __forceinline__ void mma_tf32(float* c, const uint32_t* a, const uint32_t* b) {
    asm volatile(
        "mma.sync.aligned.m16n8k8.row.col.f32.tf32.tf32.f32 "
        "{%0,%1,%2,%3}, {%4,%5,%6,%7}, {%8,%9}, {%0,%1,%2,%3};"
        : "+f"(c[0]), "+f"(c[1]), "+f"(c[2]), "+f"(c[3])
        : "r"(a[0]), "r"(a[1]), "r"(a[2]), "r"(a[3]), "r"(b[0]), "r"(b[1]));
}

__device__ __forceinline__ uint32_t f2tf(float x) {
    uint32_t r;
    asm("cvt.rna.tf32.f32 %0, %1;" : "=r"(r) : "f"(x));
    return r;
}
__device__ __forceinline__ void tf32_split(float x, uint32_t& hi, uint32_t& lo) {
    hi = f2tf(x);
    lo = f2tf(x - __uint_as_float(hi));
}
__device__ __forceinline__ void tf32_split_f(float x, float& hi, float& lo) {
    uint32_t h = f2tf(x);
    hi = __uint_as_float(h);
    lo = __uint_as_float(f2tf(x - hi));
}
__device__ __forceinline__ float2 split2(float x) {
    float hi, lo;
    tf32_split_f(x, hi, lo);
    return make_float2(hi, lo);
}

// MUFU-free 2^u for u <= 0. ~2e-6 rel accuracy.
__device__ __forceinline__ float exp2p(float u) {
    u = fmaxf(u, -126.f);
    float z = u + 12582912.f;
    int ki = __float_as_int(z) - 0x4B400000;
    float r = u - (z - 12582912.f);
    float p = 0.00133336f;
    p = fmaf(p, r, 0.00961813f);
    p = fmaf(p, r, 0.05550411f);
    p = fmaf(p, r, 0.24022651f);
    p = fmaf(p, r, 0.69314718f);
    p = fmaf(p, r, 1.0f);
    return __int_as_float(__float_as_int(p) + (ki << 23));
}

// ---------------------------------------------------------------------------
// split pass: fp32 -> float2(hi,lo).  n multiple of 1024.
// ---------------------------------------------------------------------------
__global__ void __launch_bounds__(256) split_k(
    const float* __restrict__ in, float2* __restrict__ out, int n)
{
    const int i4 = (blockIdx.x * 256 + threadIdx.x) * 4;
    if (i4 < n) {
        float4 v = *(const float4*)(in + i4);
        out[i4 + 0] = split2(v.x);
        out[i4 + 1] = split2(v.y);
        out[i4 + 2] = split2(v.z);
        out[i4 + 3] = split2(v.w);
    }
}

// ---------------------------------------------------------------------------
// transpose + split: out2[c][r] = split(in[r][c]).  grid (Cc/32, R/32)
// ---------------------------------------------------------------------------
__global__ void __launch_bounds__(256) transpose_split(
    const float* __restrict__ in, float2* __restrict__ out, int R, int Cc)
{
    __shared__ float t[32][33];
    const int c0 = blockIdx.x * 32, r0 = blockIdx.y * 32;
    const int x = threadIdx.x, y = threadIdx.y;
#pragma unroll
    for (int i = 0; i < 32; i += 8)
        t[y + i][x] = in[(size_t)(r0 + y + i) * Cc + c0 + x];
    __syncthreads();
#pragma unroll
    for (int i = 0; i < 32; i += 8)
        out[(size_t)(c0 + y + i) * R + r0 + x] = split2(t[x][y + i]);
}

// ---------------------------------------------------------------------------
// 3xTF32 GEMM on pre-split operands:
// C[M,N] = A2[M][K] @ B2[N][K]^T + bias[N], A2/B2 interleaved (hi,lo).
// CTA 128x128x16, 256 thr = 8 warps (2m x 4n), warp 64x32. cp.async 2-stage.
// ---------------------------------------------------------------------------
#define GP 18                                // float2 per smem row (144 B)
#define GSTG (128 * GP * 8)                  // 18432 B per operand-stage
#define SMEM_GEMM (4 * GSTG)                 // 73728

__global__ void __launch_bounds__(256, 2) gemm_mma(
    const float2* __restrict__ A2, const float2* __restrict__ B2,
    const float* __restrict__ bias, float* __restrict__ C,
    int N, int K)
{
    extern __shared__ char smem[];
    float2* As[2] = { (float2*)smem,              (float2*)(smem + 2 * GSTG) };
    float2* Bs[2] = { (float2*)(smem + GSTG),     (float2*)(smem + 3 * GSTG) };
    const uint32_t sAu[2] = { smem_u32(As[0]), smem_u32(As[1]) };
    const uint32_t sBu[2] = { smem_u32(Bs[0]), smem_u32(Bs[1]) };

    const int tid = threadIdx.x;
    const int lane = tid & 31;
    const int wid = tid >> 5;
    const int wm = (wid & 1) * 64;
    const int wn = (wid >> 1) * 32;
    const int g = lane >> 2;
    const int t = lane & 3;

    const int row0 = blockIdx.y * 128;
    const int col0 = blockIdx.x * 128;

    const int ldrow = tid >> 1;          // 0..127 (x... 256 thr: rows 0..127, 2 thr/row)
    const int ldch  = (tid & 1) * 4;     // chunk base: each thread 4 chunks of 16B

    float c[4][4][4];
#pragma unroll
    for (int mf = 0; mf < 4; mf++)
#pragma unroll
        for (int nf = 0; nf < 4; nf++)
#pragma unroll
            for (int i = 0; i < 4; i++) c[mf][nf][i] = 0.f;

    const int niter = K / 16;

    // one stage: 128 rows x 16 float2 = 128 rows x 8 chunks(16B). 256 threads,
    // each thread: 1 row, 4 chunks per operand.
#define LOAD_STAGE(it, buf)                                                      \
    {                                                                            \
        const int k0_ = (it) * 16;                                               \
        const uint32_t sro = (uint32_t)(ldrow * GP) * 8;                         \
        const float2* ga = A2 + (size_t)(row0 + ldrow) * K + k0_;                \
        const float2* gb = B2 + (size_t)(col0 + ldrow) * K + k0_;                \
        _Pragma("unroll")                                                        \
        for (int ch = 0; ch < 4; ch++) {                                         \
            cp_async16(sAu[buf] + sro + (ldch + ch) * 16, ga + (ldch + ch) * 2); \
            cp_async16(sBu[buf] + sro + (ldch + ch) * 16, gb + (ldch + ch) * 2); \
        }                                                                        \
        CP_COMMIT();                                                             \
    }

    LOAD_STAGE(0, 0);
    LOAD_STAGE(1, 1);
    CP_WAIT(1);
    __syncthreads();

    for (int it = 0; it < niter; it++) {
        const int buf = it & 1;
        const float2* Ab = As[buf];
        const float2* Bb = Bs[buf];

#pragma unroll
        for (int ks = 0; ks < 2; ks++) {
            const int k = ks * 8 + t;
            uint32_t ah[4][4], al[4][4], bh[4][2], bl[4][2];
#pragma unroll
            for (int mf = 0; mf < 4; mf++) {
                const int r = (wm + mf * 16 + g) * GP + k;
                float2 a0 = Ab[r];
                float2 a1 = Ab[r + 8 * GP];
                float2 a2 = Ab[r + 4];
                float2 a3 = Ab[r + 8 * GP + 4];
                ah[mf][0] = __float_as_uint(a0.x); al[mf][0] = __float_as_uint(a0.y);
                ah[mf][1] = __float_as_uint(a1.x); al[mf][1] = __float_as_uint(a1.y);
                ah[mf][2] = __float_as_uint(a2.x); al[mf][2] = __float_as_uint(a2.y);
                ah[mf][3] = __float_as_uint(a3.x); al[mf][3] = __float_as_uint(a3.y);
            }
#pragma unroll
            for (int nf = 0; nf < 4; nf++) {
                const int r = (wn + nf * 8 + g) * GP + k;
                float2 b0 = Bb[r];
                float2 b1 = Bb[r + 4];
                bh[nf][0] = __float_as_uint(b0.x); bl[nf][0] = __float_as_uint(b0.y);
                bh[nf][1] = __float_as_uint(b1.x); bl[nf][1] = __float_as_uint(b1.y);
            }
#pragma unroll
            for (int mf = 0; mf < 4; mf++)
#pragma unroll
                for (int nf = 0; nf < 4; nf++) {
                    mma_tf32(c[mf][nf], al[mf], bh[nf]);
                    mma_tf32(c[mf][nf], ah[mf], bl[nf]);
                    mma_tf32(c[mf][nf], ah[mf], bh[nf]);
                }
        }

        __syncthreads();
        if (it + 2 < niter) {
            LOAD_STAGE(it + 2, buf);
            CP_WAIT(1);
        } else {
            CP_WAIT(0);
        }
        __syncthreads();
    }
#undef LOAD_STAGE

#pragma unroll
    for (int mf = 0; mf < 4; mf++) {
        const int r0_ = row0 + wm + mf * 16 + g;
#pragma unroll
        for (int nf = 0; nf < 4; nf++) {
            const int cc = col0 + wn + nf * 8 + t * 2;
            const float b0 = bias[cc], b1 = bias[cc + 1];
            float2 lo = make_float2(c[mf][nf][0] + b0, c[mf][nf][1] + b1);
            float2 hi = make_float2(c[mf][nf][2] + b0, c[mf][nf][3] + b1);
            *(float2*)&C[(size_t)r0_ * N + cc]       = lo;
            *(float2*)&C[(size_t)(r0_ + 8) * N + cc] = hi;
        }
    }
}

// ---------------------------------------------------------------------------
// 2-term TF32 flash attention.
// S = (qh+ql)*Khi ; PV = Phi*(Vhi+Vlo).  K staged hi-only, P stored hi-only.
// 4 warps/CTA, 64 q-rows, kv tiles of 64. smem 68 KB -> 3 CTAs/SM.
// ---------------------------------------------------------------------------
#define APITCH 68
#define KHI_OFF  0
#define VTHI_OFF 4352
#define VTLO_OFF 8704
#define P_OFF    13056                     // PHI per warp [16][68]
#define ATT_FLOATS 17408
#define ATT_SMEM (ATT_FLOATS * 4)          // 69632 bytes

__global__ void __launch_bounds__(128, 3) attn_mma(
    const float* __restrict__ qkv, float* __restrict__ out)
{
    extern __shared__ float sm[];
    const int tid = threadIdx.x;
    const int lane = tid & 31;
    const int wid = tid >> 5;
    const int g = lane >> 2;
    const int t = lane & 3;

    const int bh = blockIdx.y;
    const int b = bh >> 4;
    const int h = bh & 15;
    const int qtile = (int)gridDim.x - 1 - (int)blockIdx.x;
    const int q0 = qtile * 64;

    float* PHI = sm + P_OFF + wid * 1088;

    const float QSCALE = 0.125f * 1.44269504f;
    const int grow0 = q0 + wid * 16 + g;
    const int grow1 = grow0 + 8;
    const float* q0p = qkv + (size_t)(b * TT + grow0) * C3 + h * HDIM;
    const float* q1p = q0p + (size_t)8 * C3;

    uint32_t qh[8][4], ql[8][4];
#pragma unroll
    for (int ks = 0; ks < 8; ks++) {
        tf32_split(q0p[ks * 8 + t]     * QSCALE, qh[ks][0], ql[ks][0]);
        tf32_split(q1p[ks * 8 + t]     * QSCALE, qh[ks][1], ql[ks][1]);
        tf32_split(q0p[ks * 8 + t + 4] * QSCALE, qh[ks][2], ql[ks][2]);
        tf32_split(q1p[ks * 8 + t + 4] * QSCALE, qh[ks][3], ql[ks][3]);
    }

    float o[8][4];
#pragma unroll
    for (int nf = 0; nf < 8; nf++)
#pragma unroll
        for (int i = 0; i < 4; i++) o[nf][i] = 0.f;
    float m0 = -1e30f, m1 = -1e30f, l0 = 0.f, l1 = 0.f;

    const int ntiles = qtile + 1;
    const float* kbase0 = qkv + (size_t)b * TT * C3 + CCH + h * HDIM;

    for (int tile = 0; tile < ntiles; tile++) {
        const int kv0 = tile * 64;
        const float* kb = kbase0 + (size_t)kv0 * C3;

        __syncthreads();

        // --- stage K hi-only (row-major [kv][d]) ---
#pragma unroll
        for (int i = 0; i < 8; i++) {
            const int idx = tid + i * 128;
            const int r = idx >> 4, c4 = idx & 15;
            float4 kv4 = *(const float4*)(kb + (size_t)r * C3 + c4 * 4);
            float4 kh4;
            kh4.x = __uint_as_float(f2tf(kv4.x));
            kh4.y = __uint_as_float(f2tf(kv4.y));
            kh4.z = __uint_as_float(f2tf(kv4.z));
            kh4.w = __uint_as_float(f2tf(kv4.w));
            *(float4*)&sm[KHI_OFF + r * APITCH + c4 * 4] = kh4;
        }
        // --- stage V transposed, split hi/lo ---
#pragma unroll
        for (int j = 0; j < 2; j++) {
            const int bb2 = tid + j * 128;
            const int br = (bb2 >> 4) * 4;
            const int bc = (bb2 & 15) * 4;
            const float* vb = kb + CCH;
            float4 v0 = *(const float4*)(vb + (size_t)(br + 0) * C3 + bc);
            float4 v1 = *(const float4*)(vb + (size_t)(br + 1) * C3 + bc);
            float4 v2 = *(const float4*)(vb + (size_t)(br + 2) * C3 + bc);
            float4 v3 = *(const float4*)(vb + (size_t)(br + 3) * C3 + bc);
            float4 rowv[4] = {
                make_float4(v0.x, v1.x, v2.x, v3.x),
                make_float4(v0.y, v1.y, v2.y, v3.y),
                make_float4(v0.z, v1.z, v2.z, v3.z),
                make_float4(v0.w, v1.w, v2.w, v3.w)
            };
#pragma unroll
            for (int d = 0; d < 4; d++) {
                float4 hi4, lo4;
                tf32_split_f(rowv[d].x, hi4.x, lo4.x);
                tf32_split_f(rowv[d].y, hi4.y, lo4.y);
                tf32_split_f(rowv[d].z, hi4.z, lo4.z);
                tf32_split_f(rowv[d].w, hi4.w, lo4.w);
                *(float4*)&sm[VTHI_OFF + (bc + d) * APITCH + br] = hi4;
                *(float4*)&sm[VTLO_OFF + (bc + d) * APITCH + br] = lo4;
            }
        }
        __syncthreads();

        // --- S = Q K^T (2-term: Q exact, K hi) ---
        float s[8][4];
#pragma unroll
        for (int nf = 0; nf < 8; nf++) {
#pragma unroll
            for (int i = 0; i < 4; i++) s[nf][i] = 0.f;
            const int krow = (nf * 8 + g) * APITCH;
#pragma unroll
            for (int ks = 0; ks < 8; ks++) {
                uint32_t bh2[2];
                bh2[0] = __float_as_uint(sm[KHI_OFF + krow + ks * 8 + t]);
                bh2[1] = __float_as_uint(sm[KHI_OFF + krow + ks * 8 + t + 4]);
                mma_tf32(s[nf], ql[ks], bh2);
                mma_tf32(s[nf], qh[ks], bh2);
            }
        }

        // --- causal mask (diagonal tile only) ---
        if (tile == qtile) {
#pragma unroll
            for (int nf = 0; nf < 8; nf++) {
                const int c0 = kv0 + nf * 8 + 2 * t;
                if (c0 > grow0)     s[nf][0] = -1e30f;
                if (c0 + 1 > grow0) s[nf][1] = -1e30f;
                if (c0 > grow1)     s[nf][2] = -1e30f;
                if (c0 + 1 > grow1) s[nf][3] = -1e30f;
            }
        }

        // --- online softmax (base 2) ---
        float tm0 = -1e30f, tm1 = -1e30f;
#pragma unroll
        for (int nf = 0; nf < 8; nf++) {
            tm0 = fmaxf(tm0, fmaxf(s[nf][0], s[nf][1]));
            tm1 = fmaxf(tm1, fmaxf(s[nf][2], s[nf][3]));
        }
        tm0 = fmaxf(tm0, __shfl_xor_sync(0xffffffffu, tm0, 1));
        tm0 = fmaxf(tm0, __shfl_xor_sync(0xffffffffu, tm0, 2));
        tm1 = fmaxf(tm1, __shfl_xor_sync(0xffffffffu, tm1, 1));
        tm1 = fmaxf(tm1, __shfl_xor_sync(0xffffffffu, tm1, 2));
        const float mn0 = fmaxf(m0, tm0);
        const float mn1 = fmaxf(m1, tm1);
        const float cr0 = exp2p(m0 - mn0);
        const float cr1 = exp2p(m1 - mn1);
        m0 = mn0; m1 = mn1;
        l0 *= cr0; l1 *= cr1;
#pragma unroll
        for (int nf = 0; nf < 8; nf++) {
            o[nf][0] *= cr0; o[nf][1] *= cr0;
            o[nf][2] *= cr1; o[nf][3] *= cr1;
        }

        // --- P = 2^(s-m), hi-only to per-warp smem ---
#pragma unroll
        for (int nf = 0; nf < 8; nf++) {
            const float p0 = exp2p(s[nf][0] - m0);
            const float p1 = exp2p(s[nf][1] - m0);
            const float p2 = exp2p(s[nf][2] - m1);
            const float p3 = exp2p(s[nf][3] - m1);
            l0 += p0 + p1;
            l1 += p2 + p3;
            const int cidx = nf * 8 + 2 * t;
            *(float2*)&PHI[g * APITCH + cidx] =
                make_float2(__uint_as_float(f2tf(p0)), __uint_as_float(f2tf(p1)));
            *(float2*)&PHI[(g + 8) * APITCH + cidx] =
                make_float2(__uint_as_float(f2tf(p2)), __uint_as_float(f2tf(p3)));
        }
        __syncwarp();

        // --- O += P V (2-term: P hi, V exact) ---
#pragma unroll
        for (int ks = 0; ks < 8; ks++) {
            uint32_t pah[4];
            pah[0] = __float_as_uint(PHI[g * APITCH + ks * 8 + t]);
            pah[1] = __float_as_uint(PHI[(g + 8) * APITCH + ks * 8 + t]);
            pah[2] = __float_as_uint(PHI[g * APITCH + ks * 8 + t + 4]);
            pah[3] = __float_as_uint(PHI[(g + 8) * APITCH + ks * 8 + t + 4]);
#pragma unroll
            for (int nf = 0; nf < 8; nf++) {
                const int vrow = (nf * 8 + g) * APITCH;
                uint32_t vh[2], vl[2];
                vh[0] = __float_as_uint(sm[VTHI_OFF + vrow + ks * 8 + t]);
                vh[1] = __float_as_uint(sm[VTHI_OFF + vrow + ks * 8 + t + 4]);
                vl[0] = __float_as_uint(sm[VTLO_OFF + vrow + ks * 8 + t]);
                vl[1] = __float_as_uint(sm[VTLO_OFF + vrow + ks * 8 + t + 4]);
                mma_tf32(o[nf], pah, vl);
                mma_tf32(o[nf], pah, vh);
            }
        }
        __syncwarp();
    }

    l0 += __shfl_xor_sync(0xffffffffu, l0, 1);
    l0 += __shfl_xor_sync(0xffffffffu, l0, 2);
    l1 += __shfl_xor_sync(0xffffffffu, l1, 1);
    l1 += __shfl_xor_sync(0xffffffffu, l1, 2);
    const float inv0 = 1.f / l0;
    const float inv1 = 1.f / l1;

    float* op0 = out + (size_t)(b * TT + grow0) * CCH + h * HDIM;
    float* op1 = out + (size_t)(b * TT + grow1) * CCH + h * HDIM;
#pragma unroll
    for (int nf = 0; nf < 8; nf++) {
        const int cidx = nf * 8 + 2 * t;
        *(float2*)&op0[cidx] = make_float2(o[nf][0] * inv0, o[nf][1] * inv0);
        *(float2*)&op1[cidx] = make_float2(o[nf][2] * inv1, o[nf][3] * inv1);
    }
}

// ---------------------------------------------------------------------------
extern "C" void kernel_launch(void* const* d_in, const int* in_sizes, int n_in,
                              void* d_out, int out_size)
{
    (void)in_sizes; (void)n_in; (void)out_size;
    const float* x    = (const float*)d_in[0];
    const float* Wqkv = (const float*)d_in[1];
    const float* bqkv = (const float*)d_in[2];
    const float* Wo   = (const float*)d_in[3];
    const float* bo   = (const float*)d_in[4];
    float* out = (float*)d_out;

    float  *qkvbuf, *attbuf;
    float2 *x2, *att2, *wqkvT2, *woT2;
    cudaGetSymbolAddress((void**)&qkvbuf, g_qkv);
    cudaGetSymbolAddress((void**)&attbuf, g_att);
    cudaGetSymbolAddress((void**)&x2,     g_x2);
    cudaGetSymbolAddress((void**)&att2,   g_att2);
    cudaGetSymbolAddress((void**)&wqkvT2, g_wqkvT2);
    cudaGetSymbolAddress((void**)&woT2,   g_woT2);

    static int smem_set = 0;
    if (!smem_set) {
        cudaFuncSetAttribute(gemm_mma, cudaFuncAttributeMaxDynamicSharedMemorySize, SMEM_GEMM);
        cudaFuncSetAttribute(attn_mma, cudaFuncAttributeMaxDynamicSharedMemorySize, ATT_SMEM);
        smem_set = 1;
    }

    // 0) pre-split weights (transpose) and x
    transpose_split<<<dim3(C3 / 32, CCH / 32), dim3(32, 8)>>>(Wqkv, wqkvT2, CCH, C3);
    transpose_split<<<dim3(CCH / 32, CCH / 32), dim3(32, 8)>>>(Wo, woT2, CCH, CCH);
    split_k<<<(NTOK * CCH / 4 + 255) / 256, 256>>>(x, x2, NTOK * CCH);

    // 1) QKV projection
    gemm_mma<<<dim3(C3 / 128, NTOK / 128), 256, SMEM_GEMM>>>(x2, wqkvT2, bqkv, qkvbuf, C3, CCH);

    // 2) causal flash attention (2-term TF32)
    attn_mma<<<dim3(TT / 64, BB * HH), 128, ATT_SMEM>>>(qkvbuf, attbuf);

    // 3) split attention output, then output projection
    split_k<<<(NTOK * CCH / 4 + 255) / 256, 256>>>(attbuf, att2, NTOK * CCH);
    gemm_mma<<<dim3(CCH / 128, NTOK / 128), 256, SMEM_GEMM>>>(att2, woT2, bo, out, CCH, CCH);
}